// round 3
// baseline (speedup 1.0000x reference)
#include <cuda_runtime.h>
#include <cstdint>
#include <cstddef>

// ---------------------------------------------------------------------------
// SO3Reparameterize: z = expmap(x@Wmu+bmu) @ expmap(L @ (sqrt(softplus(x@Wd+bd))*eps))
// Fused skinny GEMM (X[65536,1024] @ W9[1024,9]) + per-row epilogue.
// R3 (= R2 re-bench after infra failure): no x smem staging (direct LDG.128),
//     split-K=4, barrier-free mainloop, 6 blocks/SM (smem = W only, 36 KB),
//     unroll 8 for deeper LDG batching.
// ---------------------------------------------------------------------------

#define K_DIM     1024
#define SPLITK    4
#define KSEG      (K_DIM / SPLITK)        // 256 k per segment
#define GROUPS    (KSEG / 4)              // 64 groups of 4 k
#define THREADS   128
#define ROWS_BLK  64                      // 32 lanes * 2 rows
#define WPACK_ELEMS ((K_DIM / 4) * 36)    // 9216 floats = 36 KB

__device__ float g_wpack[WPACK_ELEMS];

// Pack Wmu|Wd|Wl ([1024,3] each) into wpack[kb][j][4]: k-group kb (4 k),
// column j in 0..8, 4 k-values contiguous (8B halves are f32x2 pairs).
__global__ void pack_w_kernel(const float* __restrict__ Wmu,
                              const float* __restrict__ Wd,
                              const float* __restrict__ Wl) {
    int idx = blockIdx.x * blockDim.x + threadIdx.x;
    if (idx >= WPACK_ELEMS) return;
    int kb  = idx / 36;
    int rem = idx - kb * 36;
    int j   = rem >> 2;
    int kk  = rem & 3;
    int k   = kb * 4 + kk;
    float v;
    if (j < 3)      v = Wmu[k * 3 + j];
    else if (j < 6) v = Wd [k * 3 + (j - 3)];
    else            v = Wl [k * 3 + (j - 6)];
    g_wpack[idx] = v;
}

// ---- packed f32x2 FMA helpers (sm_100+) -----------------------------------
__device__ __forceinline__ void ffma2(unsigned long long& acc,
                                      unsigned long long a,
                                      unsigned long long b) {
    asm("fma.rn.f32x2 %0, %1, %2, %0;" : "+l"(acc) : "l"(a), "l"(b));
}
__device__ __forceinline__ float2 unpack2(unsigned long long v) {
    float2 r;
    asm("mov.b64 {%0, %1}, %2;" : "=f"(r.x), "=f"(r.y) : "l"(v));
    return r;
}

// ---- epilogue math ---------------------------------------------------------
__device__ __forceinline__ float softplus_f(float z) {
    return fmaxf(z, 0.0f) + log1pf(expf(-fabsf(z)));
}

__device__ __forceinline__ void rodrigues(float vx, float vy, float vz, float R[9]) {
    float th  = sqrtf(vx * vx + vy * vy + vz * vz);
    float inv = 1.0f / th;                 // reference also divides (NaN if 0)
    float kx = vx * inv, ky = vy * inv, kz = vz * inv;
    float s, c;
    sincosf(th, &s, &c);
    float ct = 1.0f - c;
    R[0] = c + ct * kx * kx;  R[1] = ct * kx * ky - s * kz;  R[2] = ct * kx * kz + s * ky;
    R[3] = ct * kx * ky + s * kz;  R[4] = c + ct * ky * ky;  R[5] = ct * ky * kz - s * kx;
    R[6] = ct * kx * kz - s * ky;  R[7] = ct * ky * kz + s * kx;  R[8] = c + ct * kz * kz;
}

__device__ __forceinline__ void row_epilogue(
    const float a[9], const float* __restrict__ eps, float* __restrict__ out,
    int grow, int B, int n,
    const float* __restrict__ bmu,
    const float* __restrict__ bd,
    const float* __restrict__ bl)
{
    float mu0 = a[0] + bmu[0], mu1 = a[1] + bmu[1], mu2 = a[2] + bmu[2];
    float s0 = sqrtf(softplus_f(a[3] + bd[0]));
    float s1 = sqrtf(softplus_f(a[4] + bd[1]));
    float s2 = sqrtf(softplus_f(a[5] + bd[2]));
    float L0 = a[6] + bl[0], L1 = a[7] + bl[1], L2 = a[8] + bl[2];

    float Rm[9];
    rodrigues(mu0, mu1, mu2, Rm);

    for (int ni = 0; ni < n; ni++) {
        const float* e = eps + ((size_t)ni * B + grow) * 3;
        float t0 = s0 * e[0], t1 = s1 * e[1], t2 = s2 * e[2];
        float v0 = t0;
        float v1 = L0 * t0 + t1;
        float v2 = L1 * t0 + L2 * t1 + t2;
        float Rv[9];
        rodrigues(v0, v1, v2, Rv);
        float* o = out + ((size_t)ni * B + grow) * 9;
#pragma unroll
        for (int i = 0; i < 3; i++) {
#pragma unroll
            for (int j = 0; j < 3; j++) {
                o[i * 3 + j] = Rm[i * 3 + 0] * Rv[0 * 3 + j]
                             + Rm[i * 3 + 1] * Rv[1 * 3 + j]
                             + Rm[i * 3 + 2] * Rv[2 * 3 + j];
            }
        }
    }
}

// ---- main fused kernel -----------------------------------------------------
extern __shared__ float smem_dyn[];   // 9216 floats: W during mainloop,
                                      // reduction buffer afterwards (reused)

__global__ __launch_bounds__(THREADS, 6)
void so3_kernel(const float* __restrict__ x,
                const float* __restrict__ eps,
                const float* __restrict__ bmu,
                const float* __restrict__ bd,
                const float* __restrict__ bl,
                float* __restrict__ out,
                int B, int n)
{
    float* ws = smem_dyn;

    const int tid   = threadIdx.x;
    const int lane  = tid & 31;            // row within block (0..31)
    const int kseg  = tid >> 5;            // k-segment (= warp id, 0..3)
    const int tile0 = blockIdx.x * ROWS_BLK;

    // stage packed W into smem (L2-resident source)
    {
        const float4* src = reinterpret_cast<const float4*>(g_wpack);
        float4*       dst = reinterpret_cast<float4*>(ws);
#pragma unroll
        for (int i = 0; i < WPACK_ELEMS / 4 / THREADS; i++)
            dst[i * THREADS + tid] = src[i * THREADS + tid];
    }
    __syncthreads();

    const int rA = tile0 + lane;           // row A (lanes cover 32 consecutive rows)
    const int rB = rA + 32;                // row B

    const ulonglong2* __restrict__ xA =
        reinterpret_cast<const ulonglong2*>(x + (size_t)rA * K_DIM + kseg * KSEG);
    const ulonglong2* __restrict__ xB =
        reinterpret_cast<const ulonglong2*>(x + (size_t)rB * K_DIM + kseg * KSEG);

    unsigned long long accA[9], accB[9];
#pragma unroll
    for (int j = 0; j < 9; j++) { accA[j] = 0ull; accB[j] = 0ull; }

    const ulonglong2* __restrict__ wp0 =
        reinterpret_cast<const ulonglong2*>(ws + (size_t)kseg * GROUPS * 36);

    // barrier-free mainloop: per group of 4 k:
    //   2 x LDG.128 (one per row), 9 x LDS.128 broadcast (W), 36 FFMA2
#pragma unroll 8
    for (int g = 0; g < GROUPS; g++) {
        ulonglong2 xa = xA[g];             // 16B = 4 floats of row A
        ulonglong2 xb = xB[g];
        const ulonglong2* wp = wp0 + g * 9;  // 9 * 16B (uniform -> broadcast)
#pragma unroll
        for (int j = 0; j < 9; j++) {
            ulonglong2 w = wp[j];          // (w_j(k0),w_j(k1)) | (w_j(k2),w_j(k3))
            ffma2(accA[j], xa.x, w.x);
            ffma2(accA[j], xa.y, w.y);
            ffma2(accB[j], xb.x, w.x);
            ffma2(accB[j], xb.y, w.y);
        }
    }

    // ---- split-K reduction via smem (reuse W region) ----
    // layout: red[(rowSlot * SPLITK + kseg) * 9 + j], rowSlot in 0..63
    __syncthreads();                       // everyone done reading W
    float* red = ws;
#pragma unroll
    for (int j = 0; j < 9; j++) {
        float2 ta = unpack2(accA[j]);
        float2 tb = unpack2(accB[j]);
        red[((lane)      * SPLITK + kseg) * 9 + j] = ta.x + ta.y;
        red[((lane + 32) * SPLITK + kseg) * 9 + j] = tb.x + tb.y;
    }
    __syncthreads();

    if (tid < ROWS_BLK) {
        float a9[9];
#pragma unroll
        for (int j = 0; j < 9; j++) {
            float s = 0.0f;
#pragma unroll
            for (int ss = 0; ss < SPLITK; ss++)
                s += red[(tid * SPLITK + ss) * 9 + j];
            a9[j] = s;
        }
        row_epilogue(a9, eps, out, tile0 + tid, B, n, bmu, bd, bl);
    }
}

// ---------------------------------------------------------------------------
extern "C" void kernel_launch(void* const* d_in, const int* in_sizes, int n_in,
                              void* d_out, int out_size) {
    const float* x   = (const float*)d_in[0];
    const float* eps = (const float*)d_in[1];
    const float* Wmu = (const float*)d_in[2];
    const float* bmu = (const float*)d_in[3];
    const float* Wd  = (const float*)d_in[4];
    const float* bd  = (const float*)d_in[5];
    const float* Wl  = (const float*)d_in[6];
    const float* bl  = (const float*)d_in[7];
    float* out = (float*)d_out;

    const int K = in_sizes[2] / 3;          // 1024
    const int B = in_sizes[0] / K;          // 65536
    const int n = in_sizes[1] / (B * 3);    // 1

    pack_w_kernel<<<(WPACK_ELEMS + 255) / 256, 256>>>(Wmu, Wd, Wl);

    const size_t smem_bytes = (size_t)WPACK_ELEMS * sizeof(float); // 36 KB
    cudaFuncSetAttribute(so3_kernel,
                         cudaFuncAttributeMaxDynamicSharedMemorySize,
                         (int)smem_bytes);

    so3_kernel<<<B / ROWS_BLK, THREADS, smem_bytes>>>(x, eps, bmu, bd, bl, out, B, n);
}

// round 4
// speedup vs baseline: 1.8135x; 1.8135x over previous
#include <cuda_runtime.h>
#include <cstdint>
#include <cstddef>

// ---------------------------------------------------------------------------
// SO3Reparameterize: z = expmap(x@Wmu+bmu) @ expmap(L @ (sqrt(softplus(x@Wd+bd))*eps))
// Fused skinny GEMM (X[65536,1024] @ W9[1024,9]) + per-row epilogue.
// R4: warp-cooperative coalesced loads (8 lanes per row -> nL=4 per LDG.128),
//     W in smem (36 KB, conflict-free LDS.128), shuffle split-k reduction,
//     no x staging, one barrier total.
// ---------------------------------------------------------------------------

#define K_DIM     1024
#define THREADS   256
#define WARPS     (THREADS / 32)            // 8
#define ROWS_PER_WARP 4
#define ROWS_BLK  (WARPS * ROWS_PER_WARP)   // 32
#define ITERS     (K_DIM / 32)              // 32 (each lane covers 4 k per iter)
#define WPACK_ELEMS ((K_DIM / 4) * 36)      // 9216 floats = 36 KB

__device__ float g_wpack[WPACK_ELEMS];

// Pack Wmu|Wd|Wl ([1024,3] each) into wpack[kb][j][4]: k-group kb (4 k),
// column j in 0..8, 4 k-values contiguous (8B halves are f32x2 pairs).
__global__ void pack_w_kernel(const float* __restrict__ Wmu,
                              const float* __restrict__ Wd,
                              const float* __restrict__ Wl) {
    int idx = blockIdx.x * blockDim.x + threadIdx.x;
    if (idx >= WPACK_ELEMS) return;
    int kb  = idx / 36;
    int rem = idx - kb * 36;
    int j   = rem >> 2;
    int kk  = rem & 3;
    int k   = kb * 4 + kk;
    float v;
    if (j < 3)      v = Wmu[k * 3 + j];
    else if (j < 6) v = Wd [k * 3 + (j - 3)];
    else            v = Wl [k * 3 + (j - 6)];
    g_wpack[idx] = v;
}

// ---- packed f32x2 FMA helpers (sm_100+) -----------------------------------
__device__ __forceinline__ void ffma2(unsigned long long& acc,
                                      unsigned long long a,
                                      unsigned long long b) {
    asm("fma.rn.f32x2 %0, %1, %2, %0;" : "+l"(acc) : "l"(a), "l"(b));
}
__device__ __forceinline__ float2 unpack2(unsigned long long v) {
    float2 r;
    asm("mov.b64 {%0, %1}, %2;" : "=f"(r.x), "=f"(r.y) : "l"(v));
    return r;
}

// ---- epilogue math ---------------------------------------------------------
__device__ __forceinline__ float softplus_f(float z) {
    return fmaxf(z, 0.0f) + log1pf(expf(-fabsf(z)));
}

__device__ __forceinline__ void rodrigues(float vx, float vy, float vz, float R[9]) {
    float th  = sqrtf(vx * vx + vy * vy + vz * vz);
    float inv = 1.0f / th;                 // reference also divides (NaN if 0)
    float kx = vx * inv, ky = vy * inv, kz = vz * inv;
    float s, c;
    sincosf(th, &s, &c);
    float ct = 1.0f - c;
    R[0] = c + ct * kx * kx;  R[1] = ct * kx * ky - s * kz;  R[2] = ct * kx * kz + s * ky;
    R[3] = ct * kx * ky + s * kz;  R[4] = c + ct * ky * ky;  R[5] = ct * ky * kz - s * kx;
    R[6] = ct * kx * kz - s * ky;  R[7] = ct * ky * kz + s * kx;  R[8] = c + ct * kz * kz;
}

__device__ __forceinline__ void row_epilogue(
    const float a[9], const float* __restrict__ eps, float* __restrict__ out,
    int grow, int B, int n,
    const float* __restrict__ bmu,
    const float* __restrict__ bd,
    const float* __restrict__ bl)
{
    float mu0 = a[0] + bmu[0], mu1 = a[1] + bmu[1], mu2 = a[2] + bmu[2];
    float s0 = sqrtf(softplus_f(a[3] + bd[0]));
    float s1 = sqrtf(softplus_f(a[4] + bd[1]));
    float s2 = sqrtf(softplus_f(a[5] + bd[2]));
    float L0 = a[6] + bl[0], L1 = a[7] + bl[1], L2 = a[8] + bl[2];

    float Rm[9];
    rodrigues(mu0, mu1, mu2, Rm);

    for (int ni = 0; ni < n; ni++) {
        const float* e = eps + ((size_t)ni * B + grow) * 3;
        float t0 = s0 * e[0], t1 = s1 * e[1], t2 = s2 * e[2];
        float v0 = t0;
        float v1 = L0 * t0 + t1;
        float v2 = L1 * t0 + L2 * t1 + t2;
        float Rv[9];
        rodrigues(v0, v1, v2, Rv);
        float* o = out + ((size_t)ni * B + grow) * 9;
#pragma unroll
        for (int i = 0; i < 3; i++) {
#pragma unroll
            for (int j = 0; j < 3; j++) {
                o[i * 3 + j] = Rm[i * 3 + 0] * Rv[0 * 3 + j]
                             + Rm[i * 3 + 1] * Rv[1 * 3 + j]
                             + Rm[i * 3 + 2] * Rv[2 * 3 + j];
            }
        }
    }
}

// ---- main fused kernel -----------------------------------------------------
extern __shared__ float smem_dyn[];   // 9216 floats: packed W

__global__ __launch_bounds__(THREADS, 4)
void so3_kernel(const float* __restrict__ x,
                const float* __restrict__ eps,
                const float* __restrict__ bmu,
                const float* __restrict__ bd,
                const float* __restrict__ bl,
                float* __restrict__ out,
                int B, int n)
{
    float* ws = smem_dyn;

    const int tid  = threadIdx.x;
    const int warp = tid >> 5;
    const int lane = tid & 31;
    const int row  = lane >> 3;           // 0..3   (row within warp)
    const int sub  = lane & 7;            // 0..7   (k-stripe within row)

    // stage packed W into smem
    {
        const float4* src = reinterpret_cast<const float4*>(g_wpack);
        float4*       dst = reinterpret_cast<float4*>(ws);
#pragma unroll
        for (int i = 0; i < WPACK_ELEMS / 4 / THREADS; i++)
            dst[i * THREADS + tid] = src[i * THREADS + tid];
    }
    __syncthreads();

    const int grow = blockIdx.x * ROWS_BLK + warp * ROWS_PER_WARP + row;

    // lane reads float4 at column sub*4 + it*32 -> 8 lanes cover 128B of one row
    const ulonglong2* __restrict__ xp =
        reinterpret_cast<const ulonglong2*>(x + (size_t)grow * K_DIM) + sub;
    // lane's W groups: kb = it*8 + sub; group kb at ulonglong2 index kb*9
    const ulonglong2* __restrict__ wg =
        reinterpret_cast<const ulonglong2*>(ws) + (size_t)sub * 9;

    unsigned long long acc[9];
#pragma unroll
    for (int j = 0; j < 9; j++) acc[j] = 0ull;

    // mainloop: per iter, warp issues 1 LDG.128 (4 lines), 9 LDS.128
    // (conflict-free, 4-lane broadcast), 18 FFMA2 per lane.
#pragma unroll 4
    for (int it = 0; it < ITERS; it++) {
        ulonglong2 xa = xp[(size_t)it * 8];              // 4 floats of this row
        const ulonglong2* wp = wg + (size_t)it * 72;     // (it*8)*9
#pragma unroll
        for (int j = 0; j < 9; j++) {
            ulonglong2 w = wp[j];       // (w_j(k0),w_j(k1)) | (w_j(k2),w_j(k3))
            ffma2(acc[j], xa.x, w.x);
            ffma2(acc[j], xa.y, w.y);
        }
    }

    // reduce packed halves, then across the 8 sub-lanes of this row
    float s[9];
#pragma unroll
    for (int j = 0; j < 9; j++) {
        float2 t = unpack2(acc[j]);
        s[j] = t.x + t.y;
    }
#pragma unroll
    for (int off = 4; off > 0; off >>= 1) {
#pragma unroll
        for (int j = 0; j < 9; j++)
            s[j] += __shfl_down_sync(0xffffffffu, s[j], off, 8);
    }

    if (sub == 0)
        row_epilogue(s, eps, out, grow, B, n, bmu, bd, bl);
}

// ---------------------------------------------------------------------------
extern "C" void kernel_launch(void* const* d_in, const int* in_sizes, int n_in,
                              void* d_out, int out_size) {
    const float* x   = (const float*)d_in[0];
    const float* eps = (const float*)d_in[1];
    const float* Wmu = (const float*)d_in[2];
    const float* bmu = (const float*)d_in[3];
    const float* Wd  = (const float*)d_in[4];
    const float* bd  = (const float*)d_in[5];
    const float* Wl  = (const float*)d_in[6];
    const float* bl  = (const float*)d_in[7];
    float* out = (float*)d_out;

    const int K = in_sizes[2] / 3;          // 1024
    const int B = in_sizes[0] / K;          // 65536
    const int n = in_sizes[1] / (B * 3);    // 1

    pack_w_kernel<<<(WPACK_ELEMS + 255) / 256, 256>>>(Wmu, Wd, Wl);

    const size_t smem_bytes = (size_t)WPACK_ELEMS * sizeof(float); // 36 KB
    cudaFuncSetAttribute(so3_kernel,
                         cudaFuncAttributeMaxDynamicSharedMemorySize,
                         (int)smem_bytes);

    so3_kernel<<<B / ROWS_BLK, THREADS, smem_bytes>>>(x, eps, bmu, bd, bl, out, B, n);
}

// round 5
// speedup vs baseline: 2.2692x; 1.2513x over previous
#include <cuda_runtime.h>
#include <cstdint>
#include <cstddef>

// ---------------------------------------------------------------------------
// SO3Reparameterize: z = expmap(x@Wmu+bmu) @ expmap(L @ (sqrt(softplus(x@Wd+bd))*eps))
// Fused skinny GEMM (X[65536,1024] @ W9[1024,9]) + per-row epilogue.
// R5: warp cooperates on 4 rows, K split 32-ways across lanes.
//     Each W LDS.128 feeds 4 rows (4x less crossbar traffic than R4).
//     Coalesced LDG.128 (512B per warp-load). Padded smem reduction (no
//     bank conflicts), separate buffer -> no extra barrier.
// ---------------------------------------------------------------------------

#define K_DIM     1024
#define THREADS   256
#define WARPS     (THREADS / 32)            // 8
#define RW        4                         // rows per warp
#define ROWS_BLK  (WARPS * RW)              // 32
#define ITERS     (K_DIM / (32 * 4))        // 8
#define WPACK_ELEMS ((K_DIM / 4) * 36)      // 9216 floats = 36 KB
#define RED_STRIDE   37                     // padded lane stride (floats)
#define RED_PER_WARP (32 * RED_STRIDE)      // 1184 floats
#define SMEM_FLOATS  (WPACK_ELEMS + WARPS * RED_PER_WARP)  // 18688 (74.75 KB)

__device__ float g_wpack[WPACK_ELEMS];

// Pack Wmu|Wd|Wl ([1024,3] each) into wpack[kb][j][4]: k-group kb (4 k),
// column j in 0..8, 4 k-values contiguous (8B halves are f32x2 pairs).
__global__ void pack_w_kernel(const float* __restrict__ Wmu,
                              const float* __restrict__ Wd,
                              const float* __restrict__ Wl) {
    int idx = blockIdx.x * blockDim.x + threadIdx.x;
    if (idx >= WPACK_ELEMS) return;
    int kb  = idx / 36;
    int rem = idx - kb * 36;
    int j   = rem >> 2;
    int kk  = rem & 3;
    int k   = kb * 4 + kk;
    float v;
    if (j < 3)      v = Wmu[k * 3 + j];
    else if (j < 6) v = Wd [k * 3 + (j - 3)];
    else            v = Wl [k * 3 + (j - 6)];
    g_wpack[idx] = v;
}

// ---- packed f32x2 FMA helpers (sm_100+) -----------------------------------
__device__ __forceinline__ void ffma2(unsigned long long& acc,
                                      unsigned long long a,
                                      unsigned long long b) {
    asm("fma.rn.f32x2 %0, %1, %2, %0;" : "+l"(acc) : "l"(a), "l"(b));
}
__device__ __forceinline__ float2 unpack2(unsigned long long v) {
    float2 r;
    asm("mov.b64 {%0, %1}, %2;" : "=f"(r.x), "=f"(r.y) : "l"(v));
    return r;
}

// ---- epilogue math ---------------------------------------------------------
__device__ __forceinline__ float softplus_f(float z) {
    return fmaxf(z, 0.0f) + log1pf(expf(-fabsf(z)));
}

__device__ __forceinline__ void rodrigues(float vx, float vy, float vz, float R[9]) {
    float th  = sqrtf(vx * vx + vy * vy + vz * vz);
    float inv = 1.0f / th;                 // reference also divides (NaN if 0)
    float kx = vx * inv, ky = vy * inv, kz = vz * inv;
    float s, c;
    sincosf(th, &s, &c);
    float ct = 1.0f - c;
    R[0] = c + ct * kx * kx;  R[1] = ct * kx * ky - s * kz;  R[2] = ct * kx * kz + s * ky;
    R[3] = ct * kx * ky + s * kz;  R[4] = c + ct * ky * ky;  R[5] = ct * ky * kz - s * kx;
    R[6] = ct * kx * kz - s * ky;  R[7] = ct * ky * kz + s * kx;  R[8] = c + ct * kz * kz;
}

__device__ __forceinline__ void row_epilogue(
    const float a[9], const float* __restrict__ eps, float* __restrict__ out,
    int grow, int B, int n,
    const float* __restrict__ bmu,
    const float* __restrict__ bd,
    const float* __restrict__ bl)
{
    float mu0 = a[0] + bmu[0], mu1 = a[1] + bmu[1], mu2 = a[2] + bmu[2];
    float s0 = sqrtf(softplus_f(a[3] + bd[0]));
    float s1 = sqrtf(softplus_f(a[4] + bd[1]));
    float s2 = sqrtf(softplus_f(a[5] + bd[2]));
    float L0 = a[6] + bl[0], L1 = a[7] + bl[1], L2 = a[8] + bl[2];

    float Rm[9];
    rodrigues(mu0, mu1, mu2, Rm);

    for (int ni = 0; ni < n; ni++) {
        const float* e = eps + ((size_t)ni * B + grow) * 3;
        float t0 = s0 * e[0], t1 = s1 * e[1], t2 = s2 * e[2];
        float v0 = t0;
        float v1 = L0 * t0 + t1;
        float v2 = L1 * t0 + L2 * t1 + t2;
        float Rv[9];
        rodrigues(v0, v1, v2, Rv);
        float* o = out + ((size_t)ni * B + grow) * 9;
#pragma unroll
        for (int i = 0; i < 3; i++) {
#pragma unroll
            for (int j = 0; j < 3; j++) {
                o[i * 3 + j] = Rm[i * 3 + 0] * Rv[0 * 3 + j]
                             + Rm[i * 3 + 1] * Rv[1 * 3 + j]
                             + Rm[i * 3 + 2] * Rv[2 * 3 + j];
            }
        }
    }
}

// ---- main fused kernel -----------------------------------------------------
extern __shared__ float smem_dyn[];   // [0,9216): packed W
                                      // [9216,18688): per-warp reduction bufs

__global__ __launch_bounds__(THREADS, 2)
void so3_kernel(const float* __restrict__ x,
                const float* __restrict__ eps,
                const float* __restrict__ bmu,
                const float* __restrict__ bd,
                const float* __restrict__ bl,
                float* __restrict__ out,
                int B, int n)
{
    float* ws = smem_dyn;

    const int tid  = threadIdx.x;
    const int warp = tid >> 5;
    const int lane = tid & 31;

    // stage packed W into smem
    {
        const float4* src = reinterpret_cast<const float4*>(g_wpack);
        float4*       dst = reinterpret_cast<float4*>(ws);
#pragma unroll
        for (int i = 0; i < WPACK_ELEMS / 4 / THREADS; i++)
            dst[i * THREADS + tid] = src[i * THREADS + tid];
    }
    __syncthreads();

    const int base_row = blockIdx.x * ROWS_BLK + warp * RW;

    const ulonglong2* __restrict__ x0 =
        reinterpret_cast<const ulonglong2*>(x + (size_t)(base_row + 0) * K_DIM);
    const ulonglong2* __restrict__ x1 =
        reinterpret_cast<const ulonglong2*>(x + (size_t)(base_row + 1) * K_DIM);
    const ulonglong2* __restrict__ x2 =
        reinterpret_cast<const ulonglong2*>(x + (size_t)(base_row + 2) * K_DIM);
    const ulonglong2* __restrict__ x3 =
        reinterpret_cast<const ulonglong2*>(x + (size_t)(base_row + 3) * K_DIM);
    const ulonglong2* __restrict__ wsu =
        reinterpret_cast<const ulonglong2*>(ws);

    unsigned long long acc[RW][9];
#pragma unroll
    for (int r = 0; r < RW; r++)
#pragma unroll
        for (int j = 0; j < 9; j++) acc[r][j] = 0ull;

    // mainloop: per iter per warp: 4 coalesced LDG.128 (512B each),
    // 9 LDS.128 (conflict-free, feeds all 4 rows), 72 FFMA2 per lane.
#pragma unroll 2
    for (int it = 0; it < ITERS; it++) {
        const int g = it * 32 + lane;                  // k-group for this lane
        ulonglong2 a0 = x0[g];
        ulonglong2 a1 = x1[g];
        ulonglong2 a2 = x2[g];
        ulonglong2 a3 = x3[g];
        const ulonglong2* wp = wsu + (size_t)g * 9;
#pragma unroll
        for (int j = 0; j < 9; j++) {
            ulonglong2 w = wp[j];   // (w_j(k0),w_j(k1)) | (w_j(k2),w_j(k3))
            ffma2(acc[0][j], a0.x, w.x);  ffma2(acc[0][j], a0.y, w.y);
            ffma2(acc[1][j], a1.x, w.x);  ffma2(acc[1][j], a1.y, w.y);
            ffma2(acc[2][j], a2.x, w.x);  ffma2(acc[2][j], a2.y, w.y);
            ffma2(acc[3][j], a3.x, w.x);  ffma2(acc[3][j], a3.y, w.y);
        }
    }

    // ---- cross-lane reduction (36 partials over 32 lanes) via padded smem --
    float* redw = smem_dyn + WPACK_ELEMS + warp * RED_PER_WARP;
#pragma unroll
    for (int r = 0; r < RW; r++)
#pragma unroll
        for (int j = 0; j < 9; j++) {
            float2 t = unpack2(acc[r][j]);
            redw[lane * RED_STRIDE + r * 9 + j] = t.x + t.y;  // conflict-free
        }
    __syncwarp();

    float out1 = 0.0f;              // output index = lane       (0..31)
#pragma unroll 8
    for (int l = 0; l < 32; l++)
        out1 += redw[l * RED_STRIDE + lane];

    float out2 = 0.0f;              // output index = 32 + lane  (lanes 0..3)
    if (lane < 4) {
#pragma unroll 8
        for (int l = 0; l < 32; l++)
            out2 += redw[l * RED_STRIDE + 32 + lane];
    }

    // gather the 9 sums of row (lane) into lanes 0..3
    float s[9];
    const int o0 = lane * 9;
#pragma unroll
    for (int j = 0; j < 9; j++) {
        int o = o0 + j;
        float v1 = __shfl_sync(0xffffffffu, out1, o & 31);
        float v2 = __shfl_sync(0xffffffffu, out2, (o - 32) & 31);
        s[j] = (o < 32) ? v1 : v2;
    }

    if (lane < RW)
        row_epilogue(s, eps, out, base_row + lane, B, n, bmu, bd, bl);
}

// ---------------------------------------------------------------------------
extern "C" void kernel_launch(void* const* d_in, const int* in_sizes, int n_in,
                              void* d_out, int out_size) {
    const float* x   = (const float*)d_in[0];
    const float* eps = (const float*)d_in[1];
    const float* Wmu = (const float*)d_in[2];
    const float* bmu = (const float*)d_in[3];
    const float* Wd  = (const float*)d_in[4];
    const float* bd  = (const float*)d_in[5];
    const float* Wl  = (const float*)d_in[6];
    const float* bl  = (const float*)d_in[7];
    float* out = (float*)d_out;

    const int K = in_sizes[2] / 3;          // 1024
    const int B = in_sizes[0] / K;          // 65536
    const int n = in_sizes[1] / (B * 3);    // 1

    pack_w_kernel<<<(WPACK_ELEMS + 255) / 256, 256>>>(Wmu, Wd, Wl);

    const size_t smem_bytes = (size_t)SMEM_FLOATS * sizeof(float); // 74.75 KB
    cudaFuncSetAttribute(so3_kernel,
                         cudaFuncAttributeMaxDynamicSharedMemorySize,
                         (int)smem_bytes);

    so3_kernel<<<B / ROWS_BLK, THREADS, smem_bytes>>>(x, eps, bmu, bd, bl, out, B, n);
}